// round 14
// baseline (speedup 1.0000x reference)
#include <cuda_runtime.h>
#include <cuda_fp16.h>
#include <math.h>

#define Bsz 128
#define Tt  256
#define Hd  1024
#define BT  (Bsz * Tt)
#define BH  (Bsz * Hd)

// Scratch (device globals). Fragments are fp16 packed as half2-in-u32.
__device__ __align__(16) unsigned g_xfrag[(size_t)BT * Hd / 2]; // x fragments (64 MiB)
__device__ __align__(16) float g_h0f[BH];                   // final h0 (fp32)
__device__ __align__(16) float g_partA[2][BH];              // Gh0 partials per K-half
__device__ __align__(16) float g_ringP[4][2][BH];           // x@Wi0 partial ring [slot][kh] (4 MiB)
__device__ __align__(16) unsigned g_h0frag[4][BH / 2];      // h0 fragments, depth-4 ring
__device__ __align__(16) unsigned g_h1frag[2][BH / 2];      // h1 fragments, parity
__device__ int g_cntA[32], g_cntP[16];                      // tile combine counters (monotonic)
__device__ int g_barA, g_barB;                              // phase barriers (64/ph, 32/ph)

// ---------------------------------------------------------------------------
__device__ __forceinline__ unsigned f2h2(float lo, float hi) {
    __half2 h = __floats2half2_rn(lo, hi);
    return *(unsigned*)&h;
}
__device__ __forceinline__ int ld_acq(const int* a) {
    int v; asm volatile("ld.acquire.gpu.s32 %0, [%1];" : "=r"(v) : "l"(a) : "memory"); return v;
}
__device__ __forceinline__ void red_release(int* a) {
    asm volatile("red.release.gpu.global.add.s32 [%0], 1;" :: "l"(a) : "memory");
}
__device__ __forceinline__ void wait_ge(const int* a, int tgt) {
    if (ld_acq(a) >= tgt) return;
    while (ld_acq(a) < tgt) __nanosleep(32);
}
__device__ __forceinline__ void prefetchL2(const void* p) {
    asm volatile("prefetch.global.L2 [%0];" :: "l"(p));
}

#define MMA_F16(C, A, B)                                                      \
    asm volatile(                                                             \
        "mma.sync.aligned.m16n8k16.row.col.f32.f16.f16.f32 "                  \
        "{%0,%1,%2,%3}, {%4,%5,%6,%7}, {%8,%9}, {%0,%1,%2,%3};"               \
        : "+f"((C)[0]), "+f"((C)[1]), "+f"((C)[2]), "+f"((C)[3])              \
        : "r"((A).x), "r"((A).y), "r"((A).z), "r"((A).w),                     \
          "r"((B).x), "r"((B).y))

// u32 index of the half2 holding A-elements (b, n),(b, n+1); n even. (validated R12)
__device__ __forceinline__ int fidx2(int b, int n) {
    int kc = n & 15;
    int lane = (b & 7) * 4 + ((kc >> 1) & 3);
    int reg  = ((b >> 3) & 1) + ((kc >> 3) << 1);
    return (((n >> 4) * 8 + (b >> 4)) * 32 + lane) * 4 + reg;
}

// ---------------------------------------------------------------------------
__global__ void init_kernel(const float* __restrict__ h0in)
{
    int idx = blockIdx.x * blockDim.x + threadIdx.x;
    if (idx < 32) g_cntA[idx] = 0;
    if (idx >= 32 && idx < 48) g_cntP[idx - 32] = 0;
    if (idx == 48) { g_barA = 0; g_barB = 0; }
    for (int e = idx; e < 2 * (BH / 2); e += gridDim.x * blockDim.x) {
        int which = e >> 16;
        int r = e & (BH / 2 - 1);
        int b = r >> 9;
        int n = (r & 511) * 2;
        unsigned v = f2h2(h0in[which * Hd + n], h0in[which * Hd + n + 1]);
        if (which == 0) g_h0frag[3][fidx2(b, n)] = v;   // Gh0(0) reads (0-1)&3 = 3
        else            g_h1frag[1][fidx2(b, n)] = v;   // B(1) reads (1-2)&1 = 1
    }
}

__global__ void xprep_kernel(const float* __restrict__ x)
{
    const int total = BT * Hd / 4;
    for (int e = blockIdx.x * blockDim.x + threadIdx.x; e < total;
         e += gridDim.x * blockDim.x) {
        int n  = (e & 255) * 4;
        int bt = e >> 8;
        int b  = bt >> 8;
        int t  = bt & 255;
        float4 v = *(const float4*)(x + (size_t)e * 4);
        unsigned* dst = g_xfrag + (size_t)t * (BH / 2);
        dst[fidx2(b, n + 0)] = f2h2(v.x, v.y);
        dst[fidx2(b, n + 2)] = f2h2(v.z, v.w);
    }
}

// ---------------------------------------------------------------------------
// Persistent kernel. 128 blocks x 512 threads, 1 block/SM.
//   bid 0..63   Gh0: 32 N-tiles(32) x 2 kh. Critical chain. 64 MMAs/warp.
//   bid 64..95  Gp:  16 N-tiles(64) x 2 kh, x@Wi0 on depth-4 ring,
//               gated barA>=64(p-3) (3 phases slack). 128 MMAs/warp.
//   bid 96..127 B:   32 fused blocks, N=32, h1 = tanh(h0@Wi1 + h1@Wh1 + b1).
//               GEMM-Wh1 early (barB slack), GEMM-Wi1 after barA>=64p.
// Sync: monotonic counters, red.release arrivals, ld.acquire polls.
//   Gh0(p): entry barA>=64p; after partial: cntA[t]>=2(p+1) || cntP[t/2]>=2(p+1)
//           || barB>=32(p-3); epilogue rows kh*64..+64 -> h0frag[p&3]; barA++.
//   Gp(p):  entry barA>=64(p-3); partial -> ringP[p&3][kh]; cntP[j]++.
//   B(p):   entry barB>=32(p-1); Wh1-GEMM; wait barA>=64p; Wi1-GEMM;
//           register epilogue -> out[:,p-1,:] + h1frag[(p-1)&1]; barB++.
// ---------------------------------------------------------------------------
extern __shared__ unsigned smemAll[];

__global__ __launch_bounds__(512, 1) void persistent_kernel(
    const float* __restrict__ Wi, const float* __restrict__ bi,
    const float* __restrict__ Wh, const float* __restrict__ bh,
    float* __restrict__ out)
{
    const int bid  = blockIdx.x;
    const int tid  = threadIdx.x;
    const int lane = tid & 31;
    const int wid  = tid >> 5;
    const int wm   = wid & 7;
    const int kg   = wid >> 3;
    const int gq   = lane >> 2, tq = lane & 3;

    if (bid < 64) {
        // ============================ Gh0 ============================
        const int tile = bid >> 1;
        const int kh   = bid & 1;
        const int n0   = tile * 32;
        const int kstart = kh * 512;
        unsigned* Wb = smemAll;                       // [32 k16][4 nt][32][2] = 32KB
        float4*  red = (float4*)(smemAll + 8192);     // 16KB

        // preload Wh0 [512 x 32] tile
#pragma unroll
        for (int i = 0; i < 4; i++) {
            int idx = tid + 512 * i;                  // 2048 = 256 kp x 8 cg
            int kp  = idx >> 3, c4 = idx & 7;
            int k0  = kstart + 2 * kp;
            float4 w0 = *(const float4*)(Wh + (size_t)k0 * Hd + n0 + c4 * 4);
            float4 w1 = *(const float4*)(Wh + (size_t)(k0 + 1) * Hd + n0 + c4 * 4);
            int k16 = (2 * kp) >> 4, kk = (2 * kp) & 15;
            float a0[4] = {w0.x, w0.y, w0.z, w0.w};
            float a1[4] = {w1.x, w1.y, w1.z, w1.w};
#pragma unroll
            for (int j = 0; j < 4; j++) {
                int nl = c4 * 4 + j, nt = nl >> 3, n_in = nl & 7;
                Wb[((k16 * 4 + nt) * 32 + n_in * 4 + ((kk & 7) >> 1)) * 2 + (kk >> 3)] =
                    f2h2(a0[j], a1[j]);
            }
        }
        __syncthreads();

        for (int p = 0; p < Tt; ++p) {
            if (tid == 0 && p > 0) wait_ge(&g_barA, 64 * p);
            __syncthreads();

            const uint4* ab = (const uint4*)g_h0frag[(p - 1) & 3]
                              + ((size_t)(kh * 32 + kg * 16) * 8 + wm) * 32 + lane;
            float c[4][4];
#pragma unroll
            for (int nt = 0; nt < 4; nt++)
#pragma unroll
                for (int r = 0; r < 4; r++) c[nt][r] = 0.0f;

            uint4 pa[8];
#pragma unroll
            for (int i = 0; i < 8; i++) pa[i] = __ldcg(ab + i * 256);
#pragma unroll
            for (int k = 0; k < 16; k++) {
                uint4 a = pa[k & 7];
                if (k < 8) pa[k & 7] = __ldcg(ab + (k + 8) * 256);
                const int kl = kg * 16 + k;
#pragma unroll
                for (int nt = 0; nt < 4; nt++) {
                    uint2 b = *(const uint2*)&Wb[((kl * 4 + nt) * 32 + lane) * 2];
                    MMA_F16(c[nt], a, b);
                }
            }

            if (kg == 1) {
#pragma unroll
                for (int nt = 0; nt < 4; nt++)
                    red[(wm * 4 + nt) * 32 + lane] =
                        make_float4(c[nt][0], c[nt][1], c[nt][2], c[nt][3]);
            }
            __syncthreads();
            if (kg == 0) {
                float* mp = g_partA[kh];
#pragma unroll
                for (int nt = 0; nt < 4; nt++) {
                    float4 r = red[(wm * 4 + nt) * 32 + lane];
                    c[nt][0] += r.x; c[nt][1] += r.y; c[nt][2] += r.z; c[nt][3] += r.w;
                    int row = wm * 16 + gq;
                    int col = n0 + nt * 8 + 2 * tq;
                    *(float2*)&mp[(size_t)row * Hd + col] = make_float2(c[nt][0], c[nt][1]);
                    *(float2*)&mp[(size_t)(row + 8) * Hd + col] = make_float2(c[nt][2], c[nt][3]);
                }
            }
            __syncthreads();

            if (tid == 0) { red_release(&g_cntA[tile]); wait_ge(&g_cntA[tile], 2 * (p + 1)); }
            else if (tid == 32) wait_ge(&g_cntP[tile >> 1], 2 * (p + 1));
            else if (tid == 64 && p >= 4) wait_ge(&g_barB, 32 * (p - 3));  // WAR h0frag[p&3]
            __syncthreads();

            // epilogue: rows kh*64..+64, 32 cols; 1 float4/thread
            {
                const int row = kh * 64 + (tid >> 3);
                const int n   = n0 + (tid & 7) * 4;
                unsigned* dstf = g_h0frag[p & 3];
                float4 a = __ldcg((const float4*)&g_partA[0][(size_t)row * Hd + n]);
                float4 b = __ldcg((const float4*)&g_partA[1][(size_t)row * Hd + n]);
                float4 q = __ldcg((const float4*)&g_ringP[p & 3][0][(size_t)row * Hd + n]);
                float4 s = __ldcg((const float4*)&g_ringP[p & 3][1][(size_t)row * Hd + n]);
                float4 b1 = *(const float4*)&bi[n];
                float4 b2 = *(const float4*)&bh[n];
                float r0 = tanhf(a.x + b.x + q.x + s.x + b1.x + b2.x);
                float r1 = tanhf(a.y + b.y + q.y + s.y + b1.y + b2.y);
                float r2 = tanhf(a.z + b.z + q.z + s.z + b1.z + b2.z);
                float r3 = tanhf(a.w + b.w + q.w + s.w + b1.w + b2.w);
                if (p == Tt - 1)
                    *(float4*)&g_h0f[(size_t)row * Hd + n] = make_float4(r0, r1, r2, r3);
                dstf[fidx2(row, n + 0)] = f2h2(r0, r1);
                dstf[fidx2(row, n + 2)] = f2h2(r2, r3);
            }
            __syncthreads();
            if (tid == 0) red_release(&g_barA);
        }
    } else if (bid < 96) {
        // ============================ Gp (ring-ahead) ============================
        const int tile = (bid - 64) >> 1;     // 0..15
        const int kh   = (bid - 64) & 1;
        const int n0   = tile * 64;
        const int kstart = kh * 512;
        unsigned* Wb = smemAll;                       // [32 k16][8 nt][32][2] = 64KB
        float4*  red = (float4*)(smemAll + 16384);    // 32KB

        // preload Wi0 [512 x 64] tile
#pragma unroll
        for (int i = 0; i < 8; i++) {
            int idx = tid + 512 * i;
            int kp  = idx >> 4, c4 = idx & 15;
            int k0  = kstart + 2 * kp;
            float4 w0 = *(const float4*)(Wi + (size_t)k0 * Hd + n0 + c4 * 4);
            float4 w1 = *(const float4*)(Wi + (size_t)(k0 + 1) * Hd + n0 + c4 * 4);
            int k16 = (2 * kp) >> 4, kk = (2 * kp) & 15;
            float a0[4] = {w0.x, w0.y, w0.z, w0.w};
            float a1[4] = {w1.x, w1.y, w1.z, w1.w};
#pragma unroll
            for (int j = 0; j < 4; j++) {
                int nl = c4 * 4 + j, nt = nl >> 3, n_in = nl & 7;
                Wb[((k16 * 8 + nt) * 32 + n_in * 4 + ((kk & 7) >> 1)) * 2 + (kk >> 3)] =
                    f2h2(a0[j], a1[j]);
            }
        }
        __syncthreads();

        for (int p = 0; p < Tt; ++p) {
            if (tid == 0 && p >= 4) wait_ge(&g_barA, 64 * (p - 3));   // ring slot WAR
            __syncthreads();

            const uint4* ab = (const uint4*)(g_xfrag + (size_t)p * (BH / 2))
                              + ((size_t)(kh * 32 + kg * 16) * 8 + wm) * 32 + lane;
            float c[8][4];
#pragma unroll
            for (int nt = 0; nt < 8; nt++)
#pragma unroll
                for (int r = 0; r < 4; r++) c[nt][r] = 0.0f;

            uint4 pa[8];
#pragma unroll
            for (int i = 0; i < 8; i++) pa[i] = __ldcg(ab + i * 256);
#pragma unroll
            for (int k = 0; k < 16; k++) {
                uint4 a = pa[k & 7];
                if (k < 8) pa[k & 7] = __ldcg(ab + (k + 8) * 256);
                const int kl = kg * 16 + k;
#pragma unroll
                for (int nt = 0; nt < 8; nt++) {
                    uint2 b = *(const uint2*)&Wb[((kl * 8 + nt) * 32 + lane) * 2];
                    MMA_F16(c[nt], a, b);
                }
            }

            if (kg == 1) {
#pragma unroll
                for (int nt = 0; nt < 8; nt++)
                    red[(wm * 8 + nt) * 32 + lane] =
                        make_float4(c[nt][0], c[nt][1], c[nt][2], c[nt][3]);
            }
            __syncthreads();
            if (kg == 0) {
                float* rp = g_ringP[p & 3][kh];
#pragma unroll
                for (int nt = 0; nt < 8; nt++) {
                    float4 r = red[(wm * 8 + nt) * 32 + lane];
                    c[nt][0] += r.x; c[nt][1] += r.y; c[nt][2] += r.z; c[nt][3] += r.w;
                    int row = wm * 16 + gq;
                    int col = n0 + nt * 8 + 2 * tq;
                    *(float2*)&rp[(size_t)row * Hd + col] = make_float2(c[nt][0], c[nt][1]);
                    *(float2*)&rp[(size_t)(row + 8) * Hd + col] = make_float2(c[nt][2], c[nt][3]);
                }
            }
            // prefetch next phase's x slice (this block's kh half: 1024 lines)
            if (p + 1 < Tt) {
                const char* nx = (const char*)(g_xfrag + (size_t)(p + 1) * (BH / 2)
                                               + (size_t)kh * 32768);
                prefetchL2(nx + (size_t)tid * 128);
                prefetchL2(nx + ((size_t)tid + 512) * 128);
            }
            __syncthreads();
            if (tid == 0) red_release(&g_cntP[tile]);
        }
    } else {
        // ============================ B (fused layer-1) ============================
        const int tile = bid - 96;            // 0..31
        const int n0   = tile * 32;
        unsigned* W1 = smemAll;               // Wh1 [1024x32] = 64KB
        unsigned* W2 = smemAll + 16384;       // Wi1 [1024x32] = 64KB
        float4*  red = (float4*)(smemAll + 32768);   // 16KB

        const float* srcs[2] = { Wh + (size_t)Hd * Hd, Wi + (size_t)Hd * Hd };
#pragma unroll
        for (int w = 0; w < 2; w++) {
            unsigned* Wb = w ? W2 : W1;
            const float* src = srcs[w];
#pragma unroll
            for (int i = 0; i < 8; i++) {
                int idx = tid + 512 * i;          // 4096 = 512 kp x 8 cg
                int kp  = idx >> 3, c4 = idx & 7;
                int k0  = 2 * kp;
                float4 w0 = *(const float4*)(src + (size_t)k0 * Hd + n0 + c4 * 4);
                float4 w1 = *(const float4*)(src + (size_t)(k0 + 1) * Hd + n0 + c4 * 4);
                int k16 = k0 >> 4, kk = k0 & 15;
                float a0[4] = {w0.x, w0.y, w0.z, w0.w};
                float a1[4] = {w1.x, w1.y, w1.z, w1.w};
#pragma unroll
                for (int j = 0; j < 4; j++) {
                    int nl = c4 * 4 + j, nt = nl >> 3, n_in = nl & 7;
                    Wb[((k16 * 4 + nt) * 32 + n_in * 4 + ((kk & 7) >> 1)) * 2 + (kk >> 3)] =
                        f2h2(a0[j], a1[j]);
                }
            }
        }
        __syncthreads();

        for (int p = 1; p <= Tt; ++p) {
            if (tid == 0 && p >= 2) wait_ge(&g_barB, 32 * (p - 1));
            __syncthreads();

            float c[4][4];
#pragma unroll
            for (int nt = 0; nt < 4; nt++)
#pragma unroll
                for (int r = 0; r < 4; r++) c[nt][r] = 0.0f;

            // GEMM 1: h1_{p-2} @ Wh1 (full K, this warp's half)
            {
                const uint4* ab = (const uint4*)g_h1frag[(p - 2) & 1]
                                  + ((size_t)(kg * 32) * 8 + wm) * 32 + lane;
                uint4 pa[8];
#pragma unroll
                for (int i = 0; i < 8; i++) pa[i] = __ldcg(ab + i * 256);
#pragma unroll
                for (int k = 0; k < 32; k++) {
                    uint4 a = pa[k & 7];
                    if (k < 24) pa[k & 7] = __ldcg(ab + (k + 8) * 256);
                    const int kl = kg * 32 + k;
#pragma unroll
                    for (int nt = 0; nt < 4; nt++) {
                        uint2 b = *(const uint2*)&W1[((kl * 4 + nt) * 32 + lane) * 2];
                        MMA_F16(c[nt], a, b);
                    }
                }
            }

            if (tid == 0) wait_ge(&g_barA, 64 * p);   // h0_{p-1} ready
            __syncthreads();

            // GEMM 2: h0_{p-1} @ Wi1 (accumulate)
            {
                const uint4* ab = (const uint4*)g_h0frag[(p - 1) & 3]
                                  + ((size_t)(kg * 32) * 8 + wm) * 32 + lane;
                uint4 pa[8];
#pragma unroll
                for (int i = 0; i < 8; i++) pa[i] = __ldcg(ab + i * 256);
#pragma unroll
                for (int k = 0; k < 32; k++) {
                    uint4 a = pa[k & 7];
                    if (k < 24) pa[k & 7] = __ldcg(ab + (k + 8) * 256);
                    const int kl = kg * 32 + k;
#pragma unroll
                    for (int nt = 0; nt < 4; nt++) {
                        uint2 b = *(const uint2*)&W2[((kl * 4 + nt) * 32 + lane) * 2];
                        MMA_F16(c[nt], a, b);
                    }
                }
            }

            if (kg == 1) {
#pragma unroll
                for (int nt = 0; nt < 4; nt++)
                    red[(wm * 4 + nt) * 32 + lane] =
                        make_float4(c[nt][0], c[nt][1], c[nt][2], c[nt][3]);
            }
            __syncthreads();

            if (kg == 0) {
                const int tt = p - 1;
                const int r0 = wm * 16 + gq, r1 = r0 + 8;
                unsigned* dstf = g_h1frag[(p - 1) & 1];
#pragma unroll
                for (int nt = 0; nt < 4; nt++) {
                    float4 rr = red[(wm * 4 + nt) * 32 + lane];
                    const int ng = n0 + nt * 8 + 2 * tq;
                    float2 bb1 = *(const float2*)&bi[Hd + ng];
                    float2 bb2 = *(const float2*)&bh[Hd + ng];
                    float bs0 = bb1.x + bb2.x, bs1 = bb1.y + bb2.y;
                    float v00 = tanhf(c[nt][0] + rr.x + bs0);
                    float v01 = tanhf(c[nt][1] + rr.y + bs1);
                    float v10 = tanhf(c[nt][2] + rr.z + bs0);
                    float v11 = tanhf(c[nt][3] + rr.w + bs1);
                    *(float2*)&out[((size_t)r0 * Tt + tt) * Hd + ng] = make_float2(v00, v01);
                    *(float2*)&out[((size_t)r1 * Tt + tt) * Hd + ng] = make_float2(v10, v11);
                    dstf[fidx2(r0, ng)] = f2h2(v00, v01);
                    dstf[fidx2(r1, ng)] = f2h2(v10, v11);
                }
            }
            __syncthreads();
            if (tid == 0) red_release(&g_barB);
        }
    }
}

// ---------------------------------------------------------------------------
__global__ void finalize_kernel(float* __restrict__ out)
{
    int idx = blockIdx.x * blockDim.x + threadIdx.x;
    if (idx >= BH) return;
    int b = idx / Hd, h = idx % Hd;
    float* hn = out + (size_t)BT * Hd;
    hn[((size_t)b * 2 + 0) * Hd + h] = g_h0f[(size_t)b * Hd + h];
    hn[((size_t)b * 2 + 1) * Hd + h] = out[((size_t)b * Tt + (Tt - 1)) * Hd + h];
}

// ---------------------------------------------------------------------------
extern "C" void kernel_launch(void* const* d_in, const int* in_sizes, int n_in,
                              void* d_out, int out_size)
{
    const float* x    = (const float*)d_in[0];   // [B,T,H]
    const float* h0in = (const float*)d_in[1];   // [1,L,H]
    const float* Wi   = (const float*)d_in[2];   // [L,H,H]
    const float* bi   = (const float*)d_in[3];   // [L,H]
    const float* Wh   = (const float*)d_in[4];   // [L,H,H]
    const float* bh   = (const float*)d_in[5];   // [L,H]
    float* out = (float*)d_out;                  // [B,T,H] then [B,L,H]

    init_kernel<<<256, 256>>>(h0in);
    xprep_kernel<<<8192, 256>>>(x);

    cudaFuncSetAttribute(persistent_kernel,
                         cudaFuncAttributeMaxDynamicSharedMemorySize, 147456);
    persistent_kernel<<<128, 512, 147456>>>(Wi, bi, Wh, bh, out);

    finalize_kernel<<<(BH + 255) / 256, 256>>>(out);
}

// round 15
// speedup vs baseline: 1.2987x; 1.2987x over previous
#include <cuda_runtime.h>
#include <cuda_fp16.h>
#include <math.h>

#define Bsz 128
#define Tt  256
#define Hd  1024
#define BT  (Bsz * Tt)
#define BH  (Bsz * Hd)

// Scratch (device globals). Fragments are fp16 packed as half2-in-u32.
__device__ __align__(16) unsigned g_xfrag[(size_t)BT * Hd / 2]; // x fragments (64 MiB)
__device__ __align__(16) float g_h0f[BH];                   // final h0 (fp32)
__device__ __align__(16) float g_part[8][BH];               // per-phase GEMM partials (fp32)
__device__ __align__(16) unsigned g_h0frag[4][BH / 2];      // h0 fragments, DEPTH-4 ring
__device__ __align__(16) unsigned g_h1frag[2][BH / 2];      // h1 fragments, parity
__device__ int g_cntA[16], g_cntB[16];                      // tile combine counters
__device__ int g_barA, g_barB;                              // group phase barriers

// ---------------------------------------------------------------------------
__device__ __forceinline__ unsigned f2h2(float lo, float hi) {
    __half2 h = __floats2half2_rn(lo, hi);
    return *(unsigned*)&h;
}
__device__ __forceinline__ int ld_acq(const int* a) {
    int v; asm volatile("ld.acquire.gpu.s32 %0, [%1];" : "=r"(v) : "l"(a) : "memory"); return v;
}
__device__ __forceinline__ void red_release(int* a) {
    asm volatile("red.release.gpu.global.add.s32 [%0], 1;" :: "l"(a) : "memory");
}
__device__ __forceinline__ void wait_ge(const int* a, int tgt) {
    if (ld_acq(a) >= tgt) return;
    while (ld_acq(a) < tgt) __nanosleep(32);
}
__device__ __forceinline__ void prefetchL2(const void* p) {
    asm volatile("prefetch.global.L2 [%0];" :: "l"(p));
}

// m16n8k16 fp16 MMA, fp32 accumulate
#define MMA_F16(C, A, B)                                                      \
    asm volatile(                                                             \
        "mma.sync.aligned.m16n8k16.row.col.f32.f16.f16.f32 "                  \
        "{%0,%1,%2,%3}, {%4,%5,%6,%7}, {%8,%9}, {%0,%1,%2,%3};"               \
        : "+f"((C)[0]), "+f"((C)[1]), "+f"((C)[2]), "+f"((C)[3])              \
        : "r"((A).x), "r"((A).y), "r"((A).z), "r"((A).w),                     \
          "r"((B).x), "r"((B).y))

// u32 index of the half2 holding elements (b, n) and (b, n+1); n even.
__device__ __forceinline__ int fidx2(int b, int n) {
    int kc = n & 15;
    int lane = (b & 7) * 4 + ((kc >> 1) & 3);
    int reg  = ((b >> 3) & 1) + ((kc >> 3) << 1);
    return (((n >> 4) * 8 + (b >> 4)) * 32 + lane) * 4 + reg;
}

// ---------------------------------------------------------------------------
// Init: zero sync state, fill initial-state fragment buffers (fp16)
// ---------------------------------------------------------------------------
__global__ void init_kernel(const float* __restrict__ h0in)
{
    int idx = blockIdx.x * blockDim.x + threadIdx.x;
    if (idx < 16) { g_cntA[idx] = 0; g_cntB[idx] = 0; }
    if (idx == 16) { g_barA = 0; g_barB = 0; }
    for (int e = idx; e < 2 * (BH / 2); e += gridDim.x * blockDim.x) {
        int which = e >> 16;               // 0: layer0, 1: layer1  (BH/2 = 65536)
        int r = e & (BH / 2 - 1);
        int b = r >> 9;                    // 512 half2 per row
        int n = (r & 511) * 2;
        unsigned v = f2h2(h0in[which * Hd + n], h0in[which * Hd + n + 1]);
        if (which == 0) g_h0frag[3][fidx2(b, n)] = v;   // A(0) reads slot (0-1)&3 = 3
        else            g_h1frag[1][fidx2(b, n)] = v;
    }
}

// ---------------------------------------------------------------------------
// xprep: x [B,T,H] fp32 -> per-token fp16 fragments in g_xfrag (one-shot).
// ---------------------------------------------------------------------------
__global__ void xprep_kernel(const float* __restrict__ x)
{
    const int total = BT * Hd / 4;
    for (int e = blockIdx.x * blockDim.x + threadIdx.x; e < total;
         e += gridDim.x * blockDim.x) {
        int n  = (e & 255) * 4;
        int bt = e >> 8;
        int b  = bt >> 8;
        int t  = bt & 255;
        float4 v = *(const float4*)(x + (size_t)e * 4);
        unsigned* dst = g_xfrag + (size_t)t * (BH / 2);
        dst[fidx2(b, n + 0)] = f2h2(v.x, v.y);
        dst[fidx2(b, n + 2)] = f2h2(v.z, v.w);
    }
}

// ---------------------------------------------------------------------------
// Persistent kernel — R12 structure, h0frag deepened to a 4-slot ring so the
// A-side WAR on B is barB >= 64(p-3) (3 phases slack, pre-satisfied) instead
// of 64(p-1) (the binding cross-coupling in R12).
// Grid = 128 blocks x 512 threads, 1 block/SM.
//   part = bid/32: 0=Gh0 [A], 1=Gi1 [B], 2=Gh1 [B], 3=Gp=x_p@Wi0 [A]
//   sub = bid%32: tile = sub>>1 (N-tile of 64), kh = sub&1 (K-half of 512).
// Warp layout: wm = wid&7 (M-tile of 16), kg = wid>>3 (K-group of 256).
// ---------------------------------------------------------------------------
extern __shared__ unsigned smemAll[];   // Bw: 16384 u32 (64KB) + red: 32KB

__global__ __launch_bounds__(512, 1) void persistent_kernel(
    const float* __restrict__ Wi, const float* __restrict__ bi,
    const float* __restrict__ Wh, const float* __restrict__ bh,
    float* __restrict__ out)
{
    const int part = blockIdx.x >> 5;     // 0..3
    const int sub  = blockIdx.x & 31;
    const int tile = sub >> 1;
    const int kh   = sub & 1;
    const bool isA = (part == 0 || part == 3);

    const int tid  = threadIdx.x;
    const int lane = tid & 31;
    const int wid  = tid >> 5;
    const int wm   = wid & 7;             // M-tile (16 rows)
    const int kg   = wid >> 3;            // K-group (16 k16-steps of this K-half)
    const int n0   = tile * 64;
    const int kstart = kh * 512;

    unsigned* Bw = smemAll;                       // [32 k16][8 nt][32 lane][2 reg]
    float4*  red = (float4*)(smemAll + 16384);    // [8 wm][8 q][32 lane]

    const float* wbase = (part == 0) ? Wh
                       : (part == 1) ? Wi + (size_t)Hd * Hd
                       : (part == 2) ? Wh + (size_t)Hd * Hd
                                     : Wi;

    // ---- one-time weight preload: pack k-pairs into fp16 fragment smem ----
#pragma unroll 4
    for (int i = 0; i < 8; i++) {
        int idx = tid + 512 * i;              // 4096 = 256 k-pairs x 16 col-groups
        int kp  = idx >> 4;
        int c4  = idx & 15;
        int krow0 = kstart + 2 * kp;
        float4 w0 = *(const float4*)(wbase + (size_t)krow0 * Hd + n0 + c4 * 4);
        float4 w1 = *(const float4*)(wbase + (size_t)(krow0 + 1) * Hd + n0 + c4 * 4);
        int kk  = (2 * kp) & 15;
        int k16 = (2 * kp) >> 4;
        float a0[4] = {w0.x, w0.y, w0.z, w0.w};
        float a1[4] = {w1.x, w1.y, w1.z, w1.w};
#pragma unroll
        for (int j = 0; j < 4; j++) {
            int n  = c4 * 4 + j;
            int nt = n >> 3, n_in = n & 7;
            Bw[((k16 * 8 + nt) * 32 + n_in * 4 + ((kk & 7) >> 1)) * 2 + (kk >> 3)] =
                f2h2(a0[j], a1[j]);
        }
    }
    __syncthreads();

    float* mp = g_part[(part == 3) ? (6 + kh) : (part * 2 + kh)];

    const int pstart = isA ? 0 : 1;
    const int pend   = isA ? Tt - 1 : Tt;

    for (int p = pstart; p <= pend; ++p) {
        // ---- entry flow wait ----
        if (tid < 2) {
            if (isA) {
                if (tid == 0 && p > 0) wait_ge(&g_barA, 64 * p);
            } else {
                if (tid == 0) wait_ge(&g_barA, 64 * p);
                if (tid == 1 && p > 1) wait_ge(&g_barB, 64 * (p - 1));
            }
        }
        __syncthreads();

        const unsigned* afrag =
            (part == 0) ? g_h0frag[(p - 1) & 3] :
            (part == 1) ? g_h0frag[(p - 1) & 3] :
            (part == 2) ? g_h1frag[p & 1]
                        : g_xfrag + (size_t)p * (BH / 2);
        // warp's disjoint A stream: k16 range [kh*32 + kg*16, +16), m-tile wm
        const uint4* abase = ((const uint4*)afrag)
                             + ((size_t)(kh * 32 + kg * 16) * 8 + wm) * 32 + lane;

        float c[8][4];
#pragma unroll
        for (int nt = 0; nt < 8; nt++)
#pragma unroll
            for (int r = 0; r < 4; r++) c[nt][r] = 0.0f;

        uint4 pa[8];
#pragma unroll
        for (int i = 0; i < 8; i++)
            pa[i] = __ldcg(abase + i * 256);

#pragma unroll
        for (int k16l = 0; k16l < 16; k16l++) {
            uint4 a = pa[k16l & 7];
            if (k16l < 8)
                pa[k16l & 7] = __ldcg(abase + (k16l + 8) * 256);
            const int k16 = kg * 16 + k16l;
#pragma unroll
            for (int nt = 0; nt < 8; nt++) {
                uint2 bfr = *(const uint2*)&Bw[(((k16 << 3) + nt) * 32 + lane) * 2];
                MMA_F16(c[nt], a, bfr);
            }
        }

        // ---- kg combine: kg1 -> smem, kg0 adds; kg0 stores partial ----
        if (kg == 1) {
#pragma unroll
            for (int q = 0; q < 8; q++)
                red[(wm * 8 + q) * 32 + lane] =
                    make_float4(c[q][0], c[q][1], c[q][2], c[q][3]);
        }
        __syncthreads();
        if (kg == 0) {
#pragma unroll
            for (int q = 0; q < 8; q++) {
                float4 r = red[(wm * 8 + q) * 32 + lane];
                c[q][0] += r.x; c[q][1] += r.y; c[q][2] += r.z; c[q][3] += r.w;
            }
            const int gq = lane >> 2, tq = lane & 3;
#pragma unroll
            for (int nt = 0; nt < 8; nt++) {
                int row = wm * 16 + gq;
                int col = n0 + nt * 8 + 2 * tq;
                *(float2*)&mp[(size_t)row * Hd + col] = make_float2(c[nt][0], c[nt][1]);
                *(float2*)&mp[(size_t)(row + 8) * Hd + col] = make_float2(c[nt][2], c[nt][3]);
            }
        }

        // full L2 prefetch of next-phase x slice (part 3): 1024 lines of 128B
        if (part == 3 && p + 1 < Tt) {
            const char* nx = (const char*)(g_xfrag
                              + (size_t)(p + 1) * (BH / 2) + (size_t)kh * 32768);
#pragma unroll
            for (int i = 0; i < 2; i++)
                prefetchL2(nx + ((size_t)tid + i * 512) * 128);
        }

        // ---- tile combine sync (4 contributors); A's WAR poll in parallel ----
        __syncthreads();
        if (tid == 0) {
            int* cnt = isA ? &g_cntA[tile] : &g_cntB[tile];
            red_release(cnt);
            wait_ge(cnt, isA ? 4 * (p + 1) : 4 * p);
        } else if (tid == 32 && isA && p >= 4) {
            wait_ge(&g_barB, 64 * (p - 3));    // WAR on h0frag ring slot p&3 (3-phase slack)
        }
        __syncthreads();

        // ---- distributed epilogue: 4 blocks/tile, each 32 rows x 64 cols ----
        const int chunk = isA ? ((part == 0 ? 0 : 2) + kh)
                              : ((part - 1) * 2 + kh);
        const int row = chunk * 32 + (tid >> 4);
        const int n   = n0 + (tid & 15) * 4;
        if (isA) {
            unsigned* dstf = g_h0frag[p & 3];
            float4 a = __ldcg((const float4*)&g_part[0][(size_t)row * Hd + n]);
            float4 b = __ldcg((const float4*)&g_part[1][(size_t)row * Hd + n]);
            float4 q = __ldcg((const float4*)&g_part[6][(size_t)row * Hd + n]);
            float4 s = __ldcg((const float4*)&g_part[7][(size_t)row * Hd + n]);
            float4 b1 = *(const float4*)&bi[n];
            float4 b2 = *(const float4*)&bh[n];
            float r0 = tanhf(a.x + b.x + q.x + s.x + b1.x + b2.x);
            float r1 = tanhf(a.y + b.y + q.y + s.y + b1.y + b2.y);
            float r2 = tanhf(a.z + b.z + q.z + s.z + b1.z + b2.z);
            float r3 = tanhf(a.w + b.w + q.w + s.w + b1.w + b2.w);
            if (p == Tt - 1)
                *(float4*)&g_h0f[(size_t)row * Hd + n] = make_float4(r0, r1, r2, r3);
            dstf[fidx2(row, n + 0)] = f2h2(r0, r1);
            dstf[fidx2(row, n + 2)] = f2h2(r2, r3);
        } else {
            const int tt = p - 1;
            unsigned* dstf = g_h1frag[(p - 1) & 1];
            float4 s2 = __ldcg((const float4*)&g_part[2][(size_t)row * Hd + n]);
            float4 s3 = __ldcg((const float4*)&g_part[3][(size_t)row * Hd + n]);
            float4 s4 = __ldcg((const float4*)&g_part[4][(size_t)row * Hd + n]);
            float4 s5 = __ldcg((const float4*)&g_part[5][(size_t)row * Hd + n]);
            float4 b1 = *(const float4*)&bi[Hd + n];
            float4 b2 = *(const float4*)&bh[Hd + n];
            float r0 = tanhf(s2.x + s3.x + s4.x + s5.x + b1.x + b2.x);
            float r1 = tanhf(s2.y + s3.y + s4.y + s5.y + b1.y + b2.y);
            float r2 = tanhf(s2.z + s3.z + s4.z + s5.z + b1.z + b2.z);
            float r3 = tanhf(s2.w + s3.w + s4.w + s5.w + b1.w + b2.w);
            *(float4*)&out[((size_t)row * Tt + tt) * Hd + n] =
                make_float4(r0, r1, r2, r3);
            dstf[fidx2(row, n + 0)] = f2h2(r0, r1);
            dstf[fidx2(row, n + 2)] = f2h2(r2, r3);
        }

        // ---- group phase arrival (release publishes this block's writes) ----
        __syncthreads();
        if (tid == 0) red_release(isA ? &g_barA : &g_barB);
    }
}

// ---------------------------------------------------------------------------
// Finalize: h_n[b][0] = h0_{T-1}, h_n[b][1] = h1_{T-1} (= out[:,T-1,:])
// ---------------------------------------------------------------------------
__global__ void finalize_kernel(float* __restrict__ out)
{
    int idx = blockIdx.x * blockDim.x + threadIdx.x;
    if (idx >= BH) return;
    int b = idx / Hd, h = idx % Hd;
    float* hn = out + (size_t)BT * Hd;
    hn[((size_t)b * 2 + 0) * Hd + h] = g_h0f[(size_t)b * Hd + h];
    hn[((size_t)b * 2 + 1) * Hd + h] = out[((size_t)b * Tt + (Tt - 1)) * Hd + h];
}

// ---------------------------------------------------------------------------
extern "C" void kernel_launch(void* const* d_in, const int* in_sizes, int n_in,
                              void* d_out, int out_size)
{
    const float* x    = (const float*)d_in[0];   // [B,T,H]
    const float* h0in = (const float*)d_in[1];   // [1,L,H]
    const float* Wi   = (const float*)d_in[2];   // [L,H,H]
    const float* bi   = (const float*)d_in[3];   // [L,H]
    const float* Wh   = (const float*)d_in[4];   // [L,H,H]
    const float* bh   = (const float*)d_in[5];   // [L,H]
    float* out = (float*)d_out;                  // [B,T,H] then [B,L,H]

    init_kernel<<<256, 256>>>(h0in);
    xprep_kernel<<<8192, 256>>>(x);

    cudaFuncSetAttribute(persistent_kernel,
                         cudaFuncAttributeMaxDynamicSharedMemorySize, 98304);
    persistent_kernel<<<128, 512, 98304>>>(Wi, bi, Wh, bh, out);

    finalize_kernel<<<(BH + 255) / 256, 256>>>(out);
}